// round 14
// baseline (speedup 1.0000x reference)
#include <cuda_runtime.h>
#include <stdint.h>
#include <math.h>

#define BB 16
#define AA 3
#define HH 80
#define WW 80
#define NC 80
#define CH 85
#define MGT 32
#define NCELL 307200
#define CELLS_PER_B 19200
#define NCHUNK 1200                // chunks of 256 cells
#define CHUNKS_PER_B 75
#define EPSF 1e-8f
#define FULLM 0xffffffffu

// ---- device scratch (zero-init at load; self-cleaned each run) ----
__device__ float4   g_gt[BB * MGT];
__device__ float    g_ga[BB * MGT];
__device__ int      g_cnt[BB];
__device__ unsigned g_mask[NCELL / 32];   // fully rewritten each run
__device__ double   g_acc[6];
__device__ unsigned g_bar_arrive;
__device__ unsigned g_bar_gen;
__device__ unsigned g_done;

__device__ __forceinline__ float softplusf(float x) {
    return fmaxf(x, 0.0f) + __logf(1.0f + __expf(-fabsf(x)));
}
__device__ __forceinline__ float wmaxf(float v) {
    #pragma unroll
    for (int o = 16; o > 0; o >>= 1) v = fmaxf(v, __shfl_xor_sync(FULLM, v, o));
    return v;
}
__device__ __forceinline__ float wminf(float v) {
    #pragma unroll
    for (int o = 16; o > 0; o >>= 1) v = fminf(v, __shfl_xor_sync(FULLM, v, o));
    return v;
}
__device__ __forceinline__ float wsumf(float v) {
    #pragma unroll
    for (int o = 16; o > 0; o >>= 1) v += __shfl_xor_sync(FULLM, v, o);
    return v;
}
__device__ __forceinline__ float sel4(int k, float a, float b, float c, float d) {
    float lo = (k & 1) ? b : a;
    float hi = (k & 1) ? d : c;
    return (k & 2) ? hi : lo;
}

// L2 evict_last policy: working set (~84 MB of touched lines) fits the 126 MB
// L2; pinning it keeps replays warm. createpolicy once, cache_hint per load.
__device__ __forceinline__ unsigned long long mk_policy() {
    unsigned long long pol;
    asm("createpolicy.fractional.L2::evict_last.b64 %0, 1.0;" : "=l"(pol));
    return pol;
}
__device__ __forceinline__ float4 ldg_el4(const float4* p, unsigned long long pol) {
    float4 r;
    asm("ld.global.nc.L2::cache_hint.v4.f32 {%0,%1,%2,%3}, [%4], %5;"
        : "=f"(r.x), "=f"(r.y), "=f"(r.z), "=f"(r.w) : "l"(p), "l"(pol));
    return r;
}
__device__ __forceinline__ float ldg_el1(const float* p, unsigned long long pol) {
    float r;
    asm("ld.global.nc.L2::cache_hint.f32 %0, [%1], %2;" : "=f"(r) : "l"(p), "l"(pol));
    return r;
}

__global__ void __launch_bounds__(256)
k_all(const float* __restrict__ preds, const float* __restrict__ targets,
      float* __restrict__ out, int G)
{
    __shared__ float4 s_gt[MGT];
    __shared__ float  s_ga[MGT];
    __shared__ int    s_cnt;
    __shared__ float  s_red[6][8];

    const float AWv[3] = {10.0f, 16.0f, 33.0f};
    const float AHv[3] = {13.0f, 30.0f, 23.0f};
    const int tid = threadIdx.x, bid = blockIdx.x;
    const int lane = tid & 31, wid = tid >> 5;
    const unsigned long long pol = mk_policy();

    // ============ Phase 1: positive bitmask + GT gather ============
    for (int idx = bid * 256 + tid; idx < NCELL; idx += G * 256) {
        float tobj = ldg_el1(&targets[(size_t)idx * CH + 4], pol);
        bool pos = tobj > 0.0f;
        unsigned pm = __ballot_sync(FULLM, pos);
        if (lane == 0) g_mask[idx >> 5] = pm;
        if (pos) {
            int b  = idx / CELLS_PER_B;
            int r  = idx % CELLS_PER_B;
            int a  = r / (HH * WW);
            int hw = r % (HH * WW);
            float wx = (float)(hw % WW), hy = (float)(hw / WW);
            const float* t = targets + (size_t)idx * CH;
            float cx = (t[0] + wx) * (1.0f / WW);
            float cy = (t[1] + hy) * (1.0f / HH);
            float bw = AWv[a] * __expf(t[2]) * (1.0f / 640.0f);
            float bh = AHv[a] * __expf(t[3]) * (1.0f / 640.0f);
            int slot = atomicAdd(&g_cnt[b], 1);
            if (slot < MGT) {
                g_gt[b * MGT + slot] = make_float4(cx - 0.5f * bw, cy - 0.5f * bh,
                                                   cx + 0.5f * bw, cy + 0.5f * bh);
                g_ga[b * MGT + slot] = bw * bh;
            }
        }
    }

    // ============ Grid barrier (G blocks co-resident) ============
    __threadfence();
    __syncthreads();
    if (tid == 0) {
        unsigned old = *(volatile unsigned*)&g_bar_gen;
        if (atomicAdd(&g_bar_arrive, 1) == (unsigned)(G - 1)) {
            g_bar_arrive = 0;
            __threadfence();
            atomicAdd(&g_bar_gen, 1);
        } else {
            while (*(volatile unsigned*)&g_bar_gen == old) __nanosleep(64);
        }
        __threadfence();
    }
    __syncthreads();

    // ============ Phase 2: per-cell losses ============
    float acc0 = 0.f, acc1 = 0.f, acc2 = 0.f, acc3 = 0.f, acc4 = 0.f, acc5 = 0.f;
    int bprev = -1;

    for (int c = bid; c < NCHUNK; c += G) {
        int idx = c * 256 + tid;
        int b   = c / CHUNKS_PER_B;               // block-uniform

        // front-batch the memory: 2x LDG.128 heads + warp-uniform mask word
        size_t qw = (size_t)idx * CH;
        const float4* P4 = (const float4*)preds;
        float4 u = ldg_el4(&P4[qw >> 2], pol);
        float4 v = ldg_el4(&P4[(qw >> 2) + 1], pol);
        unsigned pmask = g_mask[idx >> 5];

        if (b != bprev) {                          // block-uniform branch
            __syncthreads();
            if (tid < MGT) { s_gt[tid] = g_gt[b * MGT + tid];
                             s_ga[tid] = g_ga[b * MGT + tid]; }
            if (tid == 0)  s_cnt = min(g_cnt[b], MGT);
            __syncthreads();
            bprev = b;
        }

        int k = idx & 3;
        float p0 = sel4(k, u.x, u.y, u.z, u.w);
        float p1 = sel4(k, u.y, u.z, u.w, v.x);
        float p2 = sel4(k, u.z, u.w, v.x, v.y);
        float p3 = sel4(k, u.w, v.x, v.y, v.z);
        float p4 = sel4(k, v.x, v.y, v.z, v.w);

        int r  = idx % CELLS_PER_B;
        int a  = r / (HH * WW);
        int hw = r % (HH * WW);
        float wx = (float)(hw % WW), hy = (float)(hw / WW);
        float aw = AWv[a], ah = AHv[a];

        // pred box
        float ex = __expf(-p0), ey = __expf(-p1);
        float rr = __fdividef(1.0f, (1.0f + ex) * (1.0f + ey));
        float sx = rr * (1.0f + ey);
        float sy = rr * (1.0f + ex);
        float pcx = (sx + wx) * (1.0f / WW);
        float pcy = (sy + hy) * (1.0f / HH);
        float pbw = aw * __expf(p2) * (1.0f / 640.0f);
        float pbh = ah * __expf(p3) * (1.0f / 640.0f);
        float px1 = pcx - 0.5f * pbw, py1 = pcy - 0.5f * pbh;
        float px2 = pcx + 0.5f * pbw, py2 = pcy + 0.5f * pbh;
        float areaP = pbw * pbh;

        bool pos = (pmask >> lane) & 1u;
        float obj_l = softplusf(p4) - p4 * (pos ? 1.0f : 0.0f);

        // exact warp bbox + area window
        float bx1 = wminf(px1), by1 = wminf(py1);
        float bx2 = wmaxf(px2), by2 = wmaxf(py2);
        float minAP = wminf(areaP), maxAP = wmaxf(areaP);

        int cnt = s_cnt;
        float4 gl = s_gt[lane];
        float  gal = s_ga[lane];
        bool cand = (lane < cnt) &&
                    (gl.x <= bx2) && (gl.z >= bx1) &&
                    (gl.y <= by2) && (gl.w >= by1) &&
                    (2.0f * gal > minAP) && (gal < 2.0f * maxAP);
        unsigned cmask = __ballot_sync(FULLM, cand);

        bool ign = false;
        unsigned m = cmask;                        // warp-uniform, smem broadcast
        while (m) {
            int i = __ffs(m) - 1; m &= m - 1;
            float4 g  = s_gt[i];
            float gar = s_ga[i];
            float iw = fmaxf(fminf(px2, g.z) - fmaxf(px1, g.x), 0.0f);
            float ih = fmaxf(fminf(py2, g.w) - fmaxf(py1, g.y), 0.0f);
            float inter = iw * ih;
            // iou > 0.5  <=>  3*inter > areaP + areaG + eps
            ign |= (3.0f * inter > areaP + gar + EPSF);
        }

        float giou_l = 0.0f, cls_sum = 0.0f;
        if (pos) {
            const float* t = targets + qw;
            float tcx = (t[0] + wx) * (1.0f / WW);
            float tcy = (t[1] + hy) * (1.0f / HH);
            float tbw = aw * __expf(t[2]) * (1.0f / 640.0f);
            float tbh = ah * __expf(t[3]) * (1.0f / 640.0f);
            float tx1 = tcx - 0.5f * tbw, ty1 = tcy - 0.5f * tbh;
            float tx2 = tcx + 0.5f * tbw, ty2 = tcy + 0.5f * tbh;
            float areaT = tbw * tbh;
            float iw = fmaxf(fminf(px2, tx2) - fmaxf(px1, tx1), 0.0f);
            float ih = fmaxf(fminf(py2, ty2) - fmaxf(py1, ty1), 0.0f);
            float inter = iw * ih;
            float uni = areaP + areaT - inter;
            float iou = inter / (uni + EPSF);
            float cw  = fmaxf(fmaxf(px2, tx2) - fminf(px1, tx1), 0.0f);
            float chh = fmaxf(fmaxf(py2, ty2) - fminf(py1, ty1), 0.0f);
            float areaC = cw * chh;
            giou_l = 1.0f - (iou - (areaC - uni) / (areaC + EPSF));

            const float* pf = preds + qw;
            #pragma unroll 4
            for (int cc = 0; cc < NC; cc++) {
                float x  = __ldg(&pf[5 + cc]);
                float tc = __ldg(&t[5 + cc]);
                cls_sum += softplusf(x) - x * tc;
            }
        }

        float posf = pos ? 1.0f : 0.0f;
        float negf = (!pos && !ign) ? 1.0f : 0.0f;
        acc0 += posf;
        acc1 += giou_l;
        acc2 += obj_l * posf;
        acc3 += obj_l * negf;
        acc4 += negf;
        acc5 += cls_sum;
    }

    // ============ Block reduction + spread atomics ============
    float vals[6] = {acc0, acc1, acc2, acc3, acc4, acc5};
    #pragma unroll
    for (int kk = 0; kk < 6; kk++) {
        float v = wsumf(vals[kk]);
        if (lane == 0) s_red[kk][wid] = v;
    }
    __syncthreads();
    if (wid == 0 && lane < 6) {
        float v = 0.0f;
        #pragma unroll
        for (int jj = 0; jj < 8; jj++) v += s_red[lane][jj];
        atomicAdd(&g_acc[lane], (double)v);
    }
    __syncthreads();

    // ============ Last-block finalize + self-clean ============
    if (tid == 0) {
        __threadfence();
        if (atomicAdd(&g_done, 1) == (unsigned)(G - 1)) {
            double npos = atomicAdd(&g_acc[0], 0.0);
            double gsum = atomicAdd(&g_acc[1], 0.0);
            double pobj = atomicAdd(&g_acc[2], 0.0);
            double nobj = atomicAdd(&g_acc[3], 0.0);
            double nneg = atomicAdd(&g_acc[4], 0.0);
            double csum = atomicAdd(&g_acc[5], 0.0);
            float giou_v = (float)(gsum / (npos + (double)EPSF));
            float obj_v  = (float)((5.0 * pobj + nobj) / (5.0 * npos + nneg + (double)EPSF));
            float cls_v  = (float)(csum / (npos + (double)EPSF));
            out[0] = giou_v + obj_v + cls_v;
            out[1] = giou_v;
            out[2] = obj_v;
            out[3] = cls_v;
            // re-zero scratch for next graph replay
            #pragma unroll
            for (int kk = 0; kk < 6; kk++) g_acc[kk] = 0.0;
            #pragma unroll
            for (int bb2 = 0; bb2 < BB; bb2++) g_cnt[bb2] = 0;
            g_done = 0;
            __threadfence();
        }
    }
}

extern "C" void kernel_launch(void* const* d_in, const int* in_sizes, int n_in,
                              void* d_out, int out_size) {
    const float* preds   = (const float*)d_in[0];
    const float* targets = (const float*)d_in[1];
    float* out = (float*)d_out;

    int dev = 0;
    cudaGetDevice(&dev);
    int sms = 148;
    cudaDeviceGetAttribute(&sms, cudaDevAttrMultiProcessorCount, dev);
    int occ = 1;
    cudaOccupancyMaxActiveBlocksPerMultiprocessor(&occ, k_all, 256, 0);
    if (occ < 1) occ = 1;
    long long g = (long long)sms * occ;
    if (g > NCHUNK) g = NCHUNK;
    int G = (int)g;

    k_all<<<G, 256>>>(preds, targets, out, G);
}

// round 15
// speedup vs baseline: 1.0012x; 1.0012x over previous
#include <cuda_runtime.h>
#include <stdint.h>
#include <math.h>

#define BB 16
#define AA 3
#define HH 80
#define WW 80
#define NC 80
#define CH 85
#define MGT 32
#define NCELL 307200
#define CELLS_PER_B 19200
#define NCHUNK 1200                // chunks of 256 cells
#define CHUNKS_PER_B 75
#define EPSF 1e-8f
#define FULLM 0xffffffffu

// ---- device scratch (zero-init at load; self-cleaned each run) ----
__device__ float4   g_gt[BB * MGT];
__device__ float    g_ga[BB * MGT];
__device__ int      g_cnt[BB];
__device__ unsigned g_mask[NCELL / 32];   // fully rewritten each run
__device__ double   g_acc[6];
__device__ unsigned g_bar_arrive;
__device__ unsigned g_bar_gen;
__device__ unsigned g_done;

__device__ __forceinline__ float softplusf(float x) {
    return fmaxf(x, 0.0f) + __logf(1.0f + __expf(-fabsf(x)));
}
__device__ __forceinline__ float wmaxf(float v) {
    #pragma unroll
    for (int o = 16; o > 0; o >>= 1) v = fmaxf(v, __shfl_xor_sync(FULLM, v, o));
    return v;
}
__device__ __forceinline__ float wminf(float v) {
    #pragma unroll
    for (int o = 16; o > 0; o >>= 1) v = fminf(v, __shfl_xor_sync(FULLM, v, o));
    return v;
}
__device__ __forceinline__ float wsumf(float v) {
    #pragma unroll
    for (int o = 16; o > 0; o >>= 1) v += __shfl_xor_sync(FULLM, v, o);
    return v;
}
__device__ __forceinline__ float sel4(int k, float a, float b, float c, float d) {
    float lo = (k & 1) ? b : a;
    float hi = (k & 1) ? d : c;
    return (k & 2) ? hi : lo;
}

// Sector-granular loads: .cg (L2-only) avoids the .nc/texture path's full-line
// (128B) miss promotion — the pattern only needs ~30MB of 32B sectors, not 84MB.
__device__ __forceinline__ float4 ldcg4(const float4* p) {
    float4 r;
    asm("ld.global.cg.v4.f32 {%0,%1,%2,%3}, [%4];"
        : "=f"(r.x), "=f"(r.y), "=f"(r.z), "=f"(r.w) : "l"(p));
    return r;
}
__device__ __forceinline__ float ldcg1(const float* p) {
    float r;
    asm("ld.global.cg.f32 %0, [%1];" : "=f"(r) : "l"(p));
    return r;
}

__global__ void __launch_bounds__(256)
k_all(const float* __restrict__ preds, const float* __restrict__ targets,
      float* __restrict__ out, int G)
{
    __shared__ float4 s_gt[MGT];
    __shared__ float  s_ga[MGT];
    __shared__ int    s_cnt;
    __shared__ float  s_red[6][8];

    const float AWv[3] = {10.0f, 16.0f, 33.0f};
    const float AHv[3] = {13.0f, 30.0f, 23.0f};
    const int tid = threadIdx.x, bid = blockIdx.x;
    const int lane = tid & 31, wid = tid >> 5;

    // ============ Phase 1: positive bitmask + GT gather ============
    for (int idx = bid * 256 + tid; idx < NCELL; idx += G * 256) {
        float tobj = ldcg1(&targets[(size_t)idx * CH + 4]);
        bool pos = tobj > 0.0f;
        unsigned pm = __ballot_sync(FULLM, pos);
        if (lane == 0) g_mask[idx >> 5] = pm;
        if (pos) {
            int b  = idx / CELLS_PER_B;
            int r  = idx % CELLS_PER_B;
            int a  = r / (HH * WW);
            int hw = r % (HH * WW);
            float wx = (float)(hw % WW), hy = (float)(hw / WW);
            const float* t = targets + (size_t)idx * CH;
            float cx = (t[0] + wx) * (1.0f / WW);
            float cy = (t[1] + hy) * (1.0f / HH);
            float bw = AWv[a] * __expf(t[2]) * (1.0f / 640.0f);
            float bh = AHv[a] * __expf(t[3]) * (1.0f / 640.0f);
            int slot = atomicAdd(&g_cnt[b], 1);
            if (slot < MGT) {
                g_gt[b * MGT + slot] = make_float4(cx - 0.5f * bw, cy - 0.5f * bh,
                                                   cx + 0.5f * bw, cy + 0.5f * bh);
                g_ga[b * MGT + slot] = bw * bh;
            }
        }
    }

    // ============ Grid barrier (G blocks co-resident) ============
    __threadfence();
    __syncthreads();
    if (tid == 0) {
        unsigned old = *(volatile unsigned*)&g_bar_gen;
        if (atomicAdd(&g_bar_arrive, 1) == (unsigned)(G - 1)) {
            g_bar_arrive = 0;
            __threadfence();
            atomicAdd(&g_bar_gen, 1);
        } else {
            while (*(volatile unsigned*)&g_bar_gen == old) __nanosleep(64);
        }
        __threadfence();
    }
    __syncthreads();

    // ============ Phase 2: per-cell losses ============
    float acc0 = 0.f, acc1 = 0.f, acc2 = 0.f, acc3 = 0.f, acc4 = 0.f, acc5 = 0.f;
    int bprev = -1;

    for (int c = bid; c < NCHUNK; c += G) {
        int idx = c * 256 + tid;
        int b   = c / CHUNKS_PER_B;               // block-uniform

        // front-batch the memory: 2x 16B sector-granular loads + mask word
        size_t qw = (size_t)idx * CH;
        const float4* P4 = (const float4*)preds;
        float4 u = ldcg4(&P4[qw >> 2]);
        float4 v = ldcg4(&P4[(qw >> 2) + 1]);
        unsigned pmask = g_mask[idx >> 5];

        if (b != bprev) {                          // block-uniform branch
            __syncthreads();
            if (tid < MGT) { s_gt[tid] = g_gt[b * MGT + tid];
                             s_ga[tid] = g_ga[b * MGT + tid]; }
            if (tid == 0)  s_cnt = min(g_cnt[b], MGT);
            __syncthreads();
            bprev = b;
        }

        int k = idx & 3;
        float p0 = sel4(k, u.x, u.y, u.z, u.w);
        float p1 = sel4(k, u.y, u.z, u.w, v.x);
        float p2 = sel4(k, u.z, u.w, v.x, v.y);
        float p3 = sel4(k, u.w, v.x, v.y, v.z);
        float p4 = sel4(k, v.x, v.y, v.z, v.w);

        int r  = idx % CELLS_PER_B;
        int a  = r / (HH * WW);
        int hw = r % (HH * WW);
        float wx = (float)(hw % WW), hy = (float)(hw / WW);
        float aw = AWv[a], ah = AHv[a];

        // pred box
        float ex = __expf(-p0), ey = __expf(-p1);
        float rr = __fdividef(1.0f, (1.0f + ex) * (1.0f + ey));
        float sx = rr * (1.0f + ey);
        float sy = rr * (1.0f + ex);
        float pcx = (sx + wx) * (1.0f / WW);
        float pcy = (sy + hy) * (1.0f / HH);
        float pbw = aw * __expf(p2) * (1.0f / 640.0f);
        float pbh = ah * __expf(p3) * (1.0f / 640.0f);
        float px1 = pcx - 0.5f * pbw, py1 = pcy - 0.5f * pbh;
        float px2 = pcx + 0.5f * pbw, py2 = pcy + 0.5f * pbh;
        float areaP = pbw * pbh;

        bool pos = (pmask >> lane) & 1u;
        float obj_l = softplusf(p4) - p4 * (pos ? 1.0f : 0.0f);

        // exact warp bbox + area window
        float bx1 = wminf(px1), by1 = wminf(py1);
        float bx2 = wmaxf(px2), by2 = wmaxf(py2);
        float minAP = wminf(areaP), maxAP = wmaxf(areaP);

        int cnt = s_cnt;
        float4 gl = s_gt[lane];
        float  gal = s_ga[lane];
        bool cand = (lane < cnt) &&
                    (gl.x <= bx2) && (gl.z >= bx1) &&
                    (gl.y <= by2) && (gl.w >= by1) &&
                    (2.0f * gal > minAP) && (gal < 2.0f * maxAP);
        unsigned cmask = __ballot_sync(FULLM, cand);

        bool ign = false;
        unsigned m = cmask;                        // warp-uniform, smem broadcast
        while (m) {
            int i = __ffs(m) - 1; m &= m - 1;
            float4 g  = s_gt[i];
            float gar = s_ga[i];
            float iw = fmaxf(fminf(px2, g.z) - fmaxf(px1, g.x), 0.0f);
            float ih = fmaxf(fminf(py2, g.w) - fmaxf(py1, g.y), 0.0f);
            float inter = iw * ih;
            // iou > 0.5  <=>  3*inter > areaP + areaG + eps
            ign |= (3.0f * inter > areaP + gar + EPSF);
        }

        float giou_l = 0.0f, cls_sum = 0.0f;
        if (pos) {
            const float* t = targets + qw;
            float tcx = (t[0] + wx) * (1.0f / WW);
            float tcy = (t[1] + hy) * (1.0f / HH);
            float tbw = aw * __expf(t[2]) * (1.0f / 640.0f);
            float tbh = ah * __expf(t[3]) * (1.0f / 640.0f);
            float tx1 = tcx - 0.5f * tbw, ty1 = tcy - 0.5f * tbh;
            float tx2 = tcx + 0.5f * tbw, ty2 = tcy + 0.5f * tbh;
            float areaT = tbw * tbh;
            float iw = fmaxf(fminf(px2, tx2) - fmaxf(px1, tx1), 0.0f);
            float ih = fmaxf(fminf(py2, ty2) - fmaxf(py1, ty1), 0.0f);
            float inter = iw * ih;
            float uni = areaP + areaT - inter;
            float iou = inter / (uni + EPSF);
            float cw  = fmaxf(fmaxf(px2, tx2) - fminf(px1, tx1), 0.0f);
            float chh = fmaxf(fmaxf(py2, ty2) - fminf(py1, ty1), 0.0f);
            float areaC = cw * chh;
            giou_l = 1.0f - (iou - (areaC - uni) / (areaC + EPSF));

            const float* pf = preds + qw;
            #pragma unroll 4
            for (int cc = 0; cc < NC; cc++) {
                float x  = __ldg(&pf[5 + cc]);
                float tc = __ldg(&t[5 + cc]);
                cls_sum += softplusf(x) - x * tc;
            }
        }

        float posf = pos ? 1.0f : 0.0f;
        float negf = (!pos && !ign) ? 1.0f : 0.0f;
        acc0 += posf;
        acc1 += giou_l;
        acc2 += obj_l * posf;
        acc3 += obj_l * negf;
        acc4 += negf;
        acc5 += cls_sum;
    }

    // ============ Block reduction + spread atomics ============
    float vals[6] = {acc0, acc1, acc2, acc3, acc4, acc5};
    #pragma unroll
    for (int kk = 0; kk < 6; kk++) {
        float v = wsumf(vals[kk]);
        if (lane == 0) s_red[kk][wid] = v;
    }
    __syncthreads();
    if (wid == 0 && lane < 6) {
        float v = 0.0f;
        #pragma unroll
        for (int jj = 0; jj < 8; jj++) v += s_red[lane][jj];
        atomicAdd(&g_acc[lane], (double)v);
    }
    __syncthreads();

    // ============ Last-block finalize + self-clean ============
    if (tid == 0) {
        __threadfence();
        if (atomicAdd(&g_done, 1) == (unsigned)(G - 1)) {
            double npos = atomicAdd(&g_acc[0], 0.0);
            double gsum = atomicAdd(&g_acc[1], 0.0);
            double pobj = atomicAdd(&g_acc[2], 0.0);
            double nobj = atomicAdd(&g_acc[3], 0.0);
            double nneg = atomicAdd(&g_acc[4], 0.0);
            double csum = atomicAdd(&g_acc[5], 0.0);
            float giou_v = (float)(gsum / (npos + (double)EPSF));
            float obj_v  = (float)((5.0 * pobj + nobj) / (5.0 * npos + nneg + (double)EPSF));
            float cls_v  = (float)(csum / (npos + (double)EPSF));
            out[0] = giou_v + obj_v + cls_v;
            out[1] = giou_v;
            out[2] = obj_v;
            out[3] = cls_v;
            // re-zero scratch for next graph replay
            #pragma unroll
            for (int kk = 0; kk < 6; kk++) g_acc[kk] = 0.0;
            #pragma unroll
            for (int bb2 = 0; bb2 < BB; bb2++) g_cnt[bb2] = 0;
            g_done = 0;
            __threadfence();
        }
    }
}

extern "C" void kernel_launch(void* const* d_in, const int* in_sizes, int n_in,
                              void* d_out, int out_size) {
    const float* preds   = (const float*)d_in[0];
    const float* targets = (const float*)d_in[1];
    float* out = (float*)d_out;

    int dev = 0;
    cudaGetDevice(&dev);
    int sms = 148;
    cudaDeviceGetAttribute(&sms, cudaDevAttrMultiProcessorCount, dev);
    int occ = 1;
    cudaOccupancyMaxActiveBlocksPerMultiprocessor(&occ, k_all, 256, 0);
    if (occ < 1) occ = 1;
    long long g = (long long)sms * occ;
    if (g > NCHUNK) g = NCHUNK;
    int G = (int)g;

    k_all<<<G, 256>>>(preds, targets, out, G);
}